// round 6
// baseline (speedup 1.0000x reference)
#include <cuda_runtime.h>

#define BB 64
#define LL 2048
#define DD 128
#define HH 4
#define AA 128
#define MM 16
#define VV 100000
#define HDIM 32

#define NPROTO ((VV + 255) / 256)     // 391
#define NGATHER (BB * 64)             // 4096
#define NATTN BB                      // 64

// ---------------- scratch (one memset-able struct + pT) ----------------
struct Acc {
    float  PhiPt[AA * MM];    // PhiP transposed [a][m]
    float  PhiQ[BB * AA];
    double sizeP[MM];
    double sumpS[BB * MM];
    unsigned int done_proto;
    unsigned int done_gather;
    unsigned int done_attn;
};
__device__ Acc  g_acc;
__device__ float g_pT[VV * MM];      // sigmoid(phi) transposed to [V][16]
__device__ float g_C[BB * HH * DD];

__device__ __forceinline__ int detect64(const void* ids) {
    const int* w = (const int*)ids;
    return (w[1] == 0 && w[3] == 0 && w[5] == 0 && w[7] == 0) ? 1 : 0;
}
__device__ __forceinline__ long long load_ll(const void* p, long long i, int is64) {
    return is64 ? ((const long long*)p)[i] : (long long)((const int*)p)[i];
}
__device__ __forceinline__ void red_add_v4(float* p, float4 v) {
    asm volatile("red.global.add.v4.f32 [%0], {%1,%2,%3,%4};"
                 :: "l"(p), "f"(v.x), "f"(v.y), "f"(v.z), "f"(v.w) : "memory");
}
// all threads' prior writes -> visible before counter inc
__device__ __forceinline__ void block_done(unsigned int* ctr) {
    __threadfence();
    __syncthreads();
    if (threadIdx.x == 0) atomicAdd(ctr, 1u);
}
// tid0 spins with acquire, then block barrier
__device__ __forceinline__ void spin_until(unsigned int* ctr, unsigned int target) {
    if (threadIdx.x == 0) {
        unsigned int v;
        do {
            asm volatile("ld.acquire.gpu.u32 %0, [%1];" : "=r"(v) : "l"(ctr));
            if (v >= target) break;
            __nanosleep(128);
        } while (true);
    }
    __syncthreads();
}

// ---------------- K1: pT = sigmoid(phi)^T, PhiPt += p @ emb, sizeP ----------------
__global__ __launch_bounds__(256) void k_proto(const float* __restrict__ phi,
                                               const float* __restrict__ emb) {
    __shared__ float  p_sh[256 * 20];             // [v][m], 80B row stride
    __shared__ double sd[16 * 8];
    cudaTriggerProgrammaticLaunchCompletion();    // early launch for dependents only
    const int tid  = threadIdx.x;
    const int lane = tid & 31;
    const int wrp  = tid >> 5;
    const int v0   = blockIdx.x << 8;
    const int nv   = (VV - v0 < 256) ? (VV - v0) : 256;

    // Phase A: accurate sigmoid -> shared; per-element double sizeP reduction
    #pragma unroll
    for (int m = 0; m < 16; m++) {
        float p = 0.f;
        if (tid < nv) {
            float x = phi[m * VV + v0 + tid];
            p = 1.f / (1.f + expf(-x));
        }
        p_sh[tid * 20 + m] = p;
        double d = (double)p;
        #pragma unroll
        for (int off = 16; off; off >>= 1) d += __shfl_xor_sync(0xffffffffu, d, off);
        if (lane == 0) sd[m * 8 + wrp] = d;
    }
    __syncthreads();
    if (tid < 16) {
        double s = 0.0;
        #pragma unroll
        for (int w = 0; w < 8; w++) s += sd[tid * 8 + w];
        atomicAdd(&g_acc.sizeP[tid], s);
    }
    for (int j = tid; j < nv * 16; j += 256)
        g_pT[v0 * 16 + j] = p_sh[(j >> 4) * 20 + (j & 15)];

    // Phase B: FFMA2 rank-update. Group g handles alternating vi; 4x unroll.
    const int a = tid & 127;
    const int g = tid >> 7;
    unsigned long long acc[8];
    #pragma unroll
    for (int i = 0; i < 8; i++) acc[i] = 0ull;

    const unsigned pbase = (unsigned)__cvta_generic_to_shared(p_sh);
    const float* ep = emb + (long long)v0 * 128 + a + g * 128;
    const int iters = nv >> 3;
    unsigned saddr = pbase + (unsigned)g * 80;
    for (int it = 0; it < iters; it++) {
        float e0 = __ldg(ep);
        float e1 = __ldg(ep + 256);
        float e2 = __ldg(ep + 512);
        float e3 = __ldg(ep + 768);
        ep += 1024;
        #pragma unroll
        for (int u = 0; u < 4; u++) {
            float e = (u == 0) ? e0 : (u == 1) ? e1 : (u == 2) ? e2 : e3;
            unsigned long long ee, p01, p23, p45, p67;
            asm("mov.b64 %0, {%1,%1};" : "=l"(ee) : "f"(e));
            unsigned ad = saddr + (unsigned)u * 160;
            asm volatile("ld.shared.v2.u64 {%0,%1}, [%2];"      : "=l"(p01), "=l"(p23) : "r"(ad));
            asm volatile("ld.shared.v2.u64 {%0,%1}, [%2+32];"   : "=l"(p45), "=l"(p67) : "r"(ad));
            asm("fma.rn.f32x2 %0, %1, %2, %0;" : "+l"(acc[0]) : "l"(p01), "l"(ee));
            asm("fma.rn.f32x2 %0, %1, %2, %0;" : "+l"(acc[1]) : "l"(p23), "l"(ee));
            asm("fma.rn.f32x2 %0, %1, %2, %0;" : "+l"(acc[2]) : "l"(p45), "l"(ee));
            asm("fma.rn.f32x2 %0, %1, %2, %0;" : "+l"(acc[3]) : "l"(p67), "l"(ee));
            asm volatile("ld.shared.v2.u64 {%0,%1}, [%2+16];"   : "=l"(p01), "=l"(p23) : "r"(ad));
            asm volatile("ld.shared.v2.u64 {%0,%1}, [%2+48];"   : "=l"(p45), "=l"(p67) : "r"(ad));
            asm("fma.rn.f32x2 %0, %1, %2, %0;" : "+l"(acc[4]) : "l"(p01), "l"(ee));
            asm("fma.rn.f32x2 %0, %1, %2, %0;" : "+l"(acc[5]) : "l"(p23), "l"(ee));
            asm("fma.rn.f32x2 %0, %1, %2, %0;" : "+l"(acc[6]) : "l"(p45), "l"(ee));
            asm("fma.rn.f32x2 %0, %1, %2, %0;" : "+l"(acc[7]) : "l"(p67), "l"(ee));
        }
        saddr += 640;
    }
    // mapping: acc0=(m0,m1) acc1=(m2,m3) acc4=(m4,m5) acc5=(m6,m7)
    //          acc2=(m8,m9) acc3=(m10,m11) acc6=(m12,m13) acc7=(m14,m15)
    float fa[16];
    {
        const int ord[8] = {0, 1, 4, 5, 2, 3, 6, 7};
        #pragma unroll
        for (int i = 0; i < 8; i++) {
            float lo, hi;
            asm("mov.b64 {%0,%1}, %2;" : "=f"(lo), "=f"(hi) : "l"(acc[ord[i]]));
            fa[2 * i] = lo; fa[2 * i + 1] = hi;
        }
    }
    __syncthreads();
    float* red = p_sh;                            // reuse as [m][a]
    if (g == 1) {
        #pragma unroll
        for (int mi = 0; mi < 16; mi++) red[mi * 128 + a] = fa[mi];
    }
    __syncthreads();
    if (g == 0) {
        #pragma unroll
        for (int mi = 0; mi < 16; mi++) fa[mi] += red[mi * 128 + a];
        float* dst = &g_acc.PhiPt[a * 16];
        red_add_v4(dst + 0,  make_float4(fa[0],  fa[1],  fa[2],  fa[3]));
        red_add_v4(dst + 4,  make_float4(fa[4],  fa[5],  fa[6],  fa[7]));
        red_add_v4(dst + 8,  make_float4(fa[8],  fa[9],  fa[10], fa[11]));
        red_add_v4(dst + 12, make_float4(fa[12], fa[13], fa[14], fa[15]));
    }
    block_done(&g_acc.done_proto);
}

// ---------------- K2: phase1 PhiQ (overlaps k_proto), spin, phase2 sumpS ----------------
__global__ __launch_bounds__(256) void k_gather(const void* __restrict__ ids,
                                                const void* __restrict__ offs,
                                                const float* __restrict__ emb) {
    __shared__ float  sred[8 * 136];
    __shared__ double sdd[8 * 17];
    cudaTriggerProgrammaticLaunchCompletion();
    const int is64 = detect64(ids);
    const int b = blockIdx.x >> 6;
    const int s = blockIdx.x & 63;
    const long long start = load_ll(offs, b,     is64);
    const long long end   = load_ll(offs, b + 1, is64);
    const long long len   = end - start;
    const long long chunk = (len + 63) >> 6;
    const long long cs = start + (long long)s * chunk;
    long long ce = cs + chunk; if (ce > end) ce = end;

    const int w = threadIdx.x >> 5, lane = threadIdx.x & 31;
    const float4* emb4 = (const float4*)emb;

    // ---- Phase 1: PhiQ (independent of k_proto) ----
    float4 aq = make_float4(0.f, 0.f, 0.f, 0.f);
    long long i = cs + w;
    for (; i + 8 < ce; i += 16) {
        int id0 = (int)load_ll(ids, i,     is64);
        int id1 = (int)load_ll(ids, i + 8, is64);
        float4 e0 = __ldg(&emb4[id0 * 32 + lane]);
        float4 e1 = __ldg(&emb4[id1 * 32 + lane]);
        aq.x += e0.x + e1.x; aq.y += e0.y + e1.y;
        aq.z += e0.z + e1.z; aq.w += e0.w + e1.w;
    }
    for (; i < ce; i += 8) {
        int id = (int)load_ll(ids, i, is64);
        float4 e = __ldg(&emb4[id * 32 + lane]);
        aq.x += e.x; aq.y += e.y; aq.z += e.z; aq.w += e.w;
    }
    ((float4*)(sred + w * 136))[lane] = aq;
    __syncthreads();
    if (threadIdx.x < 128) {
        float t = 0.f;
        #pragma unroll
        for (int w2 = 0; w2 < 8; w2++) t += sred[w2 * 136 + threadIdx.x];
        sred[threadIdx.x] = t;
    }
    __syncthreads();
    if (threadIdx.x < 32) {
        float4 v = ((float4*)sred)[threadIdx.x];
        red_add_v4(&g_acc.PhiQ[b * 128 + threadIdx.x * 4], v);
    }

    // ---- wait for k_proto (pT ready, guaranteed via flag) ----
    spin_until(&g_acc.done_proto, NPROTO);

    // ---- Phase 2: sum_p_S from pT ----
    double as = 0.0;
    i = cs + w;
    for (; i + 8 < ce; i += 16) {
        int id0 = (int)load_ll(ids, i,     is64);
        int id1 = (int)load_ll(ids, i + 8, is64);
        if (lane < 16)
            as += (double)__ldg(&g_pT[id0 * 16 + lane]) + (double)__ldg(&g_pT[id1 * 16 + lane]);
    }
    for (; i < ce; i += 8) {
        int id = (int)load_ll(ids, i, is64);
        if (lane < 16) as += (double)__ldg(&g_pT[id * 16 + lane]);
    }
    if (lane < 16) sdd[w * 17 + lane] = as;
    __syncthreads();
    if (threadIdx.x < 16) {
        double td = 0.0;
        #pragma unroll
        for (int w2 = 0; w2 < 8; w2++) td += sdd[w2 * 17 + threadIdx.x];
        atomicAdd(&g_acc.sumpS[b * 16 + threadIdx.x], td);
    }
    block_done(&g_acc.done_gather);
}

// ---------------- K3: fused AQ/BP/Vp + scores + softmax + Z + C ----------------
__global__ __launch_bounds__(128) void k_attn(const void* __restrict__ ids,
        const void* __restrict__ offs, const float* __restrict__ size_w,
        const float* __restrict__ W_A, const float* __restrict__ W_B,
        const float* __restrict__ W_val, const float* __restrict__ b_val,
        const float* __restrict__ W_out) {
    __shared__ float sPhiPt[2048];
    __shared__ float sPhiQ[128];
    __shared__ float sAQ[128];
    __shared__ float sBP[16 * 128];
    __shared__ float sVp[16 * 32];
    __shared__ float Zs[32];
    cudaTriggerProgrammaticLaunchCompletion();

    const int b = blockIdx.x;
    const int tid = threadIdx.x;

    // gather completion implies proto completion (gather spins on proto internally)
    spin_until(&g_acc.done_gather, NGATHER);

    sPhiQ[tid] = g_acc.PhiQ[b * 128 + tid];
    #pragma unroll
    for (int i = 0; i < 4; i++)
        ((float4*)sPhiPt)[tid + i * 128] = ((const float4*)g_acc.PhiPt)[tid + i * 128];
    __syncthreads();

    // AQ[a=tid]
    {
        const float4* W4 = (const float4*)(W_A + tid * 128);
        float aqv = 0.f;
        #pragma unroll 8
        for (int k = 0; k < 32; k++) {
            float4 wv = __ldg(&W4[k]);
            aqv += sPhiQ[k*4]*wv.x + sPhiQ[k*4+1]*wv.y + sPhiQ[k*4+2]*wv.z + sPhiQ[k*4+3]*wv.w;
        }
        sAQ[tid] = aqv;
    }
    // BP[m][a=tid] for all 16 m
    {
        float bp[16];
        #pragma unroll
        for (int m = 0; m < 16; m++) bp[m] = 0.f;
        const float4* W4 = (const float4*)(W_B + tid * 128);
        const float4* P4 = (const float4*)sPhiPt;
        for (int k4 = 0; k4 < 32; k4++) {
            float4 wv = __ldg(&W4[k4]);
            #pragma unroll
            for (int kk = 0; kk < 4; kk++) {
                float wk = (kk == 0) ? wv.x : (kk == 1) ? wv.y : (kk == 2) ? wv.z : wv.w;
                int k = k4 * 4 + kk;
                float4 pA = P4[k * 4 + 0], pB = P4[k * 4 + 1];
                float4 pC = P4[k * 4 + 2], pD = P4[k * 4 + 3];
                bp[0]  += pA.x * wk; bp[1]  += pA.y * wk; bp[2]  += pA.z * wk; bp[3]  += pA.w * wk;
                bp[4]  += pB.x * wk; bp[5]  += pB.y * wk; bp[6]  += pB.z * wk; bp[7]  += pB.w * wk;
                bp[8]  += pC.x * wk; bp[9]  += pC.y * wk; bp[10] += pC.z * wk; bp[11] += pC.w * wk;
                bp[12] += pD.x * wk; bp[13] += pD.y * wk; bp[14] += pD.z * wk; bp[15] += pD.w * wk;
            }
        }
        #pragma unroll
        for (int m = 0; m < 16; m++) sBP[m * 128 + tid] = bp[m];
    }
    // Vp[m][hd]: thread tid = m*8+q computes hd = q*4..q*4+3 (without b_val)
    {
        const int m = tid >> 3, q = tid & 7;
        float va[4] = {0.f, 0.f, 0.f, 0.f};
        for (int k4 = 0; k4 < 32; k4++) {
            float pm0 = sPhiPt[(k4*4+0)*16 + m];
            float pm1 = sPhiPt[(k4*4+1)*16 + m];
            float pm2 = sPhiPt[(k4*4+2)*16 + m];
            float pm3 = sPhiPt[(k4*4+3)*16 + m];
            #pragma unroll
            for (int r = 0; r < 4; r++) {
                float4 wv = __ldg(&((const float4*)(W_val + (q*4+r) * 128))[k4]);
                va[r] += pm0*wv.x + pm1*wv.y + pm2*wv.z + pm3*wv.w;
            }
        }
        #pragma unroll
        for (int r = 0; r < 4; r++) sVp[m * 32 + q*4 + r] = va[r];
    }
    __syncthreads();

    if (tid < 32) {
        const int lane = tid;
        const int is64 = detect64(ids);
        const float sizeQ = (float)(load_ll(offs, b + 1, is64) - load_ll(offs, b, is64));
        const float sw0 = size_w[0], sw1 = size_w[1];
        float s[16];
        #pragma unroll
        for (int m = 0; m < 16; m++) {
            float part = 0.f;
            #pragma unroll
            for (int a = lane; a < 128; a += 32) part += sAQ[a] * sBP[m * 128 + a];
            #pragma unroll
            for (int off = 16; off; off >>= 1) part += __shfl_xor_sync(0xffffffffu, part, off);
            double sizeP = g_acc.sizeP[m];
            double sump  = g_acc.sumpS[b * 16 + m];
            double delta = (double)sizeQ + sizeP - 2.0 * sump;
            s[m] = (float)(-0.3 * delta + (double)part
                           + (double)sw0 * (double)sizeQ + (double)sw1 * sizeP);
        }
        float mx = s[0];
        #pragma unroll
        for (int m = 1; m < 16; m++) mx = fmaxf(mx, s[m]);
        float sum = 0.f;
        #pragma unroll
        for (int m = 0; m < 16; m++) { s[m] = expf(s[m] - mx); sum += s[m]; }
        const float inv = 1.f / sum;
        const float bvv = b_val[lane];
        float z = 0.f;
        #pragma unroll
        for (int m = 0; m < 16; m++) z += s[m] * inv * (sVp[m * 32 + lane] + bvv);
        Zs[lane] = z;
    }
    __syncthreads();
    const int j = tid;
    const float4* Wo4 = (const float4*)(W_out + j * 128);
    const float4* Z4  = (const float4*)Zs;
    #pragma unroll
    for (int h = 0; h < 4; h++) {
        float acc = 0.f;
        #pragma unroll
        for (int d = 0; d < 8; d++) {
            float4 wv = __ldg(&Wo4[h * 8 + d]);
            float4 zv = Z4[d];
            acc += zv.x*wv.x + zv.y*wv.y + zv.z*wv.z + zv.w*wv.w;
        }
        g_C[b * 512 + h * 128 + j] = acc;
    }
    block_done(&g_acc.done_attn);
}

// ---------------- K4: gates from ts (overlaps upstream), spin, apply C ----------------
__global__ __launch_bounds__(256) void k_tokens(const float* __restrict__ ts,
        const float* __restrict__ W_gate, const float* __restrict__ b_gate,
        const float* __restrict__ b_out, float* __restrict__ out) {
    __shared__ float wg[512];
    __shared__ float bo[128];
    __shared__ float bg[4];
    cudaTriggerProgrammaticLaunchCompletion();
    const int tid = threadIdx.x;
    wg[tid] = W_gate[tid];
    wg[tid + 256] = W_gate[tid + 256];
    if (tid < 128) bo[tid] = b_out[tid];
    if (tid < 4)   bg[tid] = b_gate[tid];
    __syncthreads();

    const int w = tid >> 5, lane = tid & 31;
    const int token = blockIdx.x * 8 + w;
    const int b = token >> 11;                       // L = 2048
    const float4* ts4 = (const float4*)ts;
    const float4 x = __ldg(&ts4[(long long)token * 32 + lane]);

    float g[4];
    const float4* wg4 = (const float4*)wg;
    #pragma unroll
    for (int h = 0; h < 4; h++) {
        float4 wv = wg4[h * 32 + lane];
        g[h] = x.x * wv.x + x.y * wv.y + x.z * wv.z + x.w * wv.w;
    }
    #pragma unroll
    for (int off = 16; off; off >>= 1) {
        #pragma unroll
        for (int h = 0; h < 4; h++) g[h] += __shfl_xor_sync(0xffffffffu, g[h], off);
    }
    #pragma unroll
    for (int h = 0; h < 4; h++) g[h] += bg[h];
    float mx = fmaxf(fmaxf(g[0], g[1]), fmaxf(g[2], g[3]));
    float sum = 0.f;
    #pragma unroll
    for (int h = 0; h < 4; h++) { g[h] = expf(g[h] - mx); sum += g[h]; }
    const float inv = 1.f / sum;

    spin_until(&g_acc.done_attn, NATTN);             // wait for g_C

    const float4* C4 = (const float4*)(g_C + b * 512);
    float4 o = ((const float4*)bo)[lane];
    #pragma unroll
    for (int h = 0; h < 4; h++) {
        float4 c = __ldg(&C4[h * 32 + lane]);
        float gh = g[h] * inv;
        o.x += gh * c.x; o.y += gh * c.y; o.z += gh * c.z; o.w += gh * c.w;
    }
    ((float4*)out)[(long long)token * 32 + lane] = o;
}

// ---------------- launch ----------------
static void launch_pdl(void* fn, dim3 grid, dim3 block, void** args) {
    cudaLaunchConfig_t cfg = {};
    cudaLaunchAttribute attr[1];
    attr[0].id = cudaLaunchAttributeProgrammaticStreamSerialization;
    attr[0].val.programmaticStreamSerializationAllowed = 1;
    cfg.gridDim = grid; cfg.blockDim = block;
    cfg.attrs = attr; cfg.numAttrs = 1;
    cfg.stream = 0;
    cudaLaunchKernelExC(&cfg, fn, args);
}

extern "C" void kernel_launch(void* const* d_in, const int* in_sizes, int n_in,
                              void* d_out, int out_size) {
    const float* ts    = (const float*)d_in[0];
    const void*  ids   = d_in[1];
    const void*  offs  = d_in[2];
    const float* emb   = (const float*)d_in[3];
    const float* phi   = (const float*)d_in[4];
    const float* W_A   = (const float*)d_in[5];
    const float* W_B   = (const float*)d_in[6];
    const float* W_val = (const float*)d_in[7];
    const float* b_val = (const float*)d_in[8];
    const float* W_g   = (const float*)d_in[9];
    const float* b_g   = (const float*)d_in[10];
    const float* W_o   = (const float*)d_in[11];
    const float* b_o   = (const float*)d_in[12];
    const float* szw   = (const float*)d_in[13];
    float* outp = (float*)d_out;

    void* accp = nullptr;
    cudaGetSymbolAddress(&accp, g_acc);
    cudaMemsetAsync(accp, 0, sizeof(Acc), 0);

    k_proto<<<NPROTO, 256>>>(phi, emb);

    {
        void* args[] = {(void*)&ids, (void*)&offs, (void*)&emb};
        launch_pdl((void*)k_gather, dim3(NGATHER), dim3(256), args);
    }
    {
        void* args[] = {(void*)&ids, (void*)&offs, (void*)&szw, (void*)&W_A,
                        (void*)&W_B, (void*)&W_val, (void*)&b_val, (void*)&W_o};
        launch_pdl((void*)k_attn, dim3(NATTN), dim3(128), args);
    }
    {
        void* args[] = {(void*)&ts, (void*)&W_g, (void*)&b_g, (void*)&b_o, (void*)&outp};
        launch_pdl((void*)k_tokens, dim3((BB * LL) / 8), dim3(256), args);
    }
}

// round 9
// speedup vs baseline: 1.8425x; 1.8425x over previous
#include <cuda_runtime.h>

#define BB 64
#define LL 2048
#define DD 128
#define HH 4
#define AA 128
#define MM 16
#define VV 100000
#define HDIM 32

// ---------------- scratch (one memset-able struct + pT) ----------------
struct Acc {
    float  PhiPt[AA * MM];    // PhiP transposed [a][m]
    float  PhiQ[BB * AA];
    double sizeP[MM];
    double sumpS[BB * MM];
};
__device__ Acc  g_acc;
__device__ float g_pT[VV * MM];      // sigmoid(phi) transposed to [V][16]
__device__ float g_C[BB * HH * DD];

__device__ __forceinline__ int detect64(const void* ids) {
    const int* w = (const int*)ids;
    return (w[1] == 0 && w[3] == 0 && w[5] == 0 && w[7] == 0) ? 1 : 0;
}
__device__ __forceinline__ long long load_ll(const void* p, long long i, int is64) {
    return is64 ? ((const long long*)p)[i] : (long long)((const int*)p)[i];
}
__device__ __forceinline__ void red_add_v4(float* p, float4 v) {
    asm volatile("red.global.add.v4.f32 [%0], {%1,%2,%3,%4};"
                 :: "l"(p), "f"(v.x), "f"(v.y), "f"(v.z), "f"(v.w) : "memory");
}

// ---------------- K1: pT = sigmoid(phi)^T, PhiPt += p @ emb, sizeP ----------------
__global__ __launch_bounds__(256) void k_proto(const float* __restrict__ phi,
                                               const float* __restrict__ emb) {
    __shared__ float p_sh[256 * 20];              // [v][m], 80B row stride
    const int tid  = threadIdx.x;
    const int lane = tid & 31;
    const int wrp  = tid >> 5;
    const int v0   = blockIdx.x << 8;
    const int nv   = (VV - v0 < 256) ? (VV - v0) : 256;

    // Phase A: sigmoid -> shared
    #pragma unroll
    for (int m = 0; m < 16; m++) {
        float p = 0.f;
        if (tid < nv) {
            float x = phi[m * VV + v0 + tid];
            p = 1.f / (1.f + expf(-x));
        }
        p_sh[tid * 20 + m] = p;
    }
    __syncthreads();
    // sizeP: warp wrp reduces prototypes 2*wrp, 2*wrp+1 (float partials, double atomic)
    {
        const int m0 = wrp * 2;
        float s0 = 0.f, s1 = 0.f;
        for (int v = lane; v < 256; v += 32) {
            s0 += p_sh[v * 20 + m0];
            s1 += p_sh[v * 20 + m0 + 1];
        }
        #pragma unroll
        for (int off = 16; off; off >>= 1) {
            s0 += __shfl_xor_sync(0xffffffffu, s0, off);
            s1 += __shfl_xor_sync(0xffffffffu, s1, off);
        }
        if (lane == 0) {
            atomicAdd(&g_acc.sizeP[m0],     (double)s0);
            atomicAdd(&g_acc.sizeP[m0 + 1], (double)s1);
        }
    }
    // pT write (coalesced)
    for (int j = tid; j < nv * 16; j += 256)
        g_pT[v0 * 16 + j] = p_sh[(j >> 4) * 20 + (j & 15)];

    // Phase B: FFMA2 rank-update. Group g handles alternating vi; 4x unroll.
    const int a = tid & 127;
    const int g = tid >> 7;
    unsigned long long acc[8];
    #pragma unroll
    for (int i = 0; i < 8; i++) acc[i] = 0ull;

    const unsigned pbase = (unsigned)__cvta_generic_to_shared(p_sh);
    const float* ep = emb + (long long)v0 * 128 + a + g * 128;
    const int iters = nv >> 3;
    unsigned saddr = pbase + (unsigned)g * 80;
    for (int it = 0; it < iters; it++) {
        float e0 = __ldg(ep);
        float e1 = __ldg(ep + 256);
        float e2 = __ldg(ep + 512);
        float e3 = __ldg(ep + 768);
        ep += 1024;
        #pragma unroll
        for (int u = 0; u < 4; u++) {
            float e = (u == 0) ? e0 : (u == 1) ? e1 : (u == 2) ? e2 : e3;
            unsigned long long ee, p01, p23, p45, p67;
            asm("mov.b64 %0, {%1,%1};" : "=l"(ee) : "f"(e));
            unsigned ad = saddr + (unsigned)u * 160;
            asm volatile("ld.shared.v2.u64 {%0,%1}, [%2];"      : "=l"(p01), "=l"(p23) : "r"(ad));
            asm volatile("ld.shared.v2.u64 {%0,%1}, [%2+32];"   : "=l"(p45), "=l"(p67) : "r"(ad));
            asm("fma.rn.f32x2 %0, %1, %2, %0;" : "+l"(acc[0]) : "l"(p01), "l"(ee));
            asm("fma.rn.f32x2 %0, %1, %2, %0;" : "+l"(acc[1]) : "l"(p23), "l"(ee));
            asm("fma.rn.f32x2 %0, %1, %2, %0;" : "+l"(acc[2]) : "l"(p45), "l"(ee));
            asm("fma.rn.f32x2 %0, %1, %2, %0;" : "+l"(acc[3]) : "l"(p67), "l"(ee));
            asm volatile("ld.shared.v2.u64 {%0,%1}, [%2+16];"   : "=l"(p01), "=l"(p23) : "r"(ad));
            asm volatile("ld.shared.v2.u64 {%0,%1}, [%2+48];"   : "=l"(p45), "=l"(p67) : "r"(ad));
            asm("fma.rn.f32x2 %0, %1, %2, %0;" : "+l"(acc[4]) : "l"(p01), "l"(ee));
            asm("fma.rn.f32x2 %0, %1, %2, %0;" : "+l"(acc[5]) : "l"(p23), "l"(ee));
            asm("fma.rn.f32x2 %0, %1, %2, %0;" : "+l"(acc[6]) : "l"(p45), "l"(ee));
            asm("fma.rn.f32x2 %0, %1, %2, %0;" : "+l"(acc[7]) : "l"(p67), "l"(ee));
        }
        saddr += 640;
    }
    // mapping (validated round 6): acc0=(m0,m1) acc1=(m2,m3) acc4=(m4,m5) acc5=(m6,m7)
    //                              acc2=(m8,m9) acc3=(m10,m11) acc6=(m12,m13) acc7=(m14,m15)
    float fa[16];
    {
        const int ord[8] = {0, 1, 4, 5, 2, 3, 6, 7};
        #pragma unroll
        for (int i = 0; i < 8; i++) {
            float lo, hi;
            asm("mov.b64 {%0,%1}, %2;" : "=f"(lo), "=f"(hi) : "l"(acc[ord[i]]));
            fa[2 * i] = lo; fa[2 * i + 1] = hi;
        }
    }
    __syncthreads();
    float* red = p_sh;                            // reuse as [m][a]
    if (g == 1) {
        #pragma unroll
        for (int mi = 0; mi < 16; mi++) red[mi * 128 + a] = fa[mi];
    }
    __syncthreads();
    if (g == 0) {
        #pragma unroll
        for (int mi = 0; mi < 16; mi++) fa[mi] += red[mi * 128 + a];
        float* dst = &g_acc.PhiPt[a * 16];
        red_add_v4(dst + 0,  make_float4(fa[0],  fa[1],  fa[2],  fa[3]));
        red_add_v4(dst + 4,  make_float4(fa[4],  fa[5],  fa[6],  fa[7]));
        red_add_v4(dst + 8,  make_float4(fa[8],  fa[9],  fa[10], fa[11]));
        red_add_v4(dst + 12, make_float4(fa[12], fa[13], fa[14], fa[15]));
    }
}

// ---------------- K2: segment gather: PhiQ[b,:] and sum_p_S[b,m] (single pass) ----------------
__global__ __launch_bounds__(256) void k_gather(const void* __restrict__ ids,
                                                const void* __restrict__ offs,
                                                const float* __restrict__ emb) {
    __shared__ float  sred[8 * 136];
    __shared__ double sdd[8 * 17];
    const int is64 = detect64(ids);
    const int b = blockIdx.x >> 6;
    const int s = blockIdx.x & 63;
    const long long start = load_ll(offs, b,     is64);
    const long long end   = load_ll(offs, b + 1, is64);
    const long long len   = end - start;
    const long long chunk = (len + 63) >> 6;
    const long long cs = start + (long long)s * chunk;
    long long ce = cs + chunk; if (ce > end) ce = end;

    const int w = threadIdx.x >> 5, lane = threadIdx.x & 31;
    const float4* emb4 = (const float4*)emb;
    float4 aq = make_float4(0.f, 0.f, 0.f, 0.f);
    double as = 0.0;

    long long i = cs + w;
    for (; i + 8 < ce; i += 16) {
        int id0 = (int)load_ll(ids, i,     is64);
        int id1 = (int)load_ll(ids, i + 8, is64);
        float4 e0 = __ldg(&emb4[id0 * 32 + lane]);
        float4 e1 = __ldg(&emb4[id1 * 32 + lane]);
        float p0 = 0.f, p1 = 0.f;
        if (lane < 16) { p0 = __ldg(&g_pT[id0 * 16 + lane]); p1 = __ldg(&g_pT[id1 * 16 + lane]); }
        aq.x += e0.x + e1.x; aq.y += e0.y + e1.y;
        aq.z += e0.z + e1.z; aq.w += e0.w + e1.w;
        as += (double)p0 + (double)p1;
    }
    for (; i < ce; i += 8) {
        int id = (int)load_ll(ids, i, is64);
        float4 e = __ldg(&emb4[id * 32 + lane]);
        aq.x += e.x; aq.y += e.y; aq.z += e.z; aq.w += e.w;
        if (lane < 16) as += (double)__ldg(&g_pT[id * 16 + lane]);
    }
    ((float4*)(sred + w * 136))[lane] = aq;
    if (lane < 16) sdd[w * 17 + lane] = as;
    __syncthreads();
    if (threadIdx.x < 128) {
        float t = 0.f;
        #pragma unroll
        for (int w2 = 0; w2 < 8; w2++) t += sred[w2 * 136 + threadIdx.x];
        sred[threadIdx.x] = t;
    }
    if (threadIdx.x < 16) {
        double td = 0.0;
        #pragma unroll
        for (int w2 = 0; w2 < 8; w2++) td += sdd[w2 * 17 + threadIdx.x];
        atomicAdd(&g_acc.sumpS[b * 16 + threadIdx.x], td);
    }
    __syncthreads();
    if (threadIdx.x < 32) {
        float4 v = ((float4*)sred)[threadIdx.x];
        red_add_v4(&g_acc.PhiQ[b * 128 + threadIdx.x * 4], v);
    }
}

// ---------------- K3: fused AQ/BP/Vp + scores + softmax + Z + C ----------------
__global__ __launch_bounds__(128) void k_attn(const void* __restrict__ ids,
        const void* __restrict__ offs, const float* __restrict__ size_w,
        const float* __restrict__ W_A, const float* __restrict__ W_B,
        const float* __restrict__ W_val, const float* __restrict__ b_val,
        const float* __restrict__ W_out) {
    __shared__ float sPhiPt[2048];
    __shared__ float sPhiQ[128];
    __shared__ float sAQ[128];
    __shared__ float sBP[16 * 128];
    __shared__ float sVp[16 * 32];
    __shared__ float Zs[32];

    const int b = blockIdx.x;
    const int tid = threadIdx.x;

    sPhiQ[tid] = g_acc.PhiQ[b * 128 + tid];
    #pragma unroll
    for (int i = 0; i < 4; i++)
        ((float4*)sPhiPt)[tid + i * 128] = ((const float4*)g_acc.PhiPt)[tid + i * 128];
    __syncthreads();

    // AQ[a=tid]
    {
        const float4* W4 = (const float4*)(W_A + tid * 128);
        float aqv = 0.f;
        #pragma unroll 8
        for (int k = 0; k < 32; k++) {
            float4 wv = __ldg(&W4[k]);
            aqv += sPhiQ[k*4]*wv.x + sPhiQ[k*4+1]*wv.y + sPhiQ[k*4+2]*wv.z + sPhiQ[k*4+3]*wv.w;
        }
        sAQ[tid] = aqv;
    }
    // BP[m][a=tid] for all 16 m
    {
        float bp[16];
        #pragma unroll
        for (int m = 0; m < 16; m++) bp[m] = 0.f;
        const float4* W4 = (const float4*)(W_B + tid * 128);
        const float4* P4 = (const float4*)sPhiPt;
        for (int k4 = 0; k4 < 32; k4++) {
            float4 wv = __ldg(&W4[k4]);
            #pragma unroll
            for (int kk = 0; kk < 4; kk++) {
                float wk = (kk == 0) ? wv.x : (kk == 1) ? wv.y : (kk == 2) ? wv.z : wv.w;
                int k = k4 * 4 + kk;
                float4 pA = P4[k * 4 + 0], pB = P4[k * 4 + 1];
                float4 pC = P4[k * 4 + 2], pD = P4[k * 4 + 3];
                bp[0]  += pA.x * wk; bp[1]  += pA.y * wk; bp[2]  += pA.z * wk; bp[3]  += pA.w * wk;
                bp[4]  += pB.x * wk; bp[5]  += pB.y * wk; bp[6]  += pB.z * wk; bp[7]  += pB.w * wk;
                bp[8]  += pC.x * wk; bp[9]  += pC.y * wk; bp[10] += pC.z * wk; bp[11] += pC.w * wk;
                bp[12] += pD.x * wk; bp[13] += pD.y * wk; bp[14] += pD.z * wk; bp[15] += pD.w * wk;
            }
        }
        #pragma unroll
        for (int m = 0; m < 16; m++) sBP[m * 128 + tid] = bp[m];
    }
    // Vp[m][hd]: thread tid = m*8+q computes hd = q*4..q*4+3 (without b_val)
    {
        const int m = tid >> 3, q = tid & 7;
        float va[4] = {0.f, 0.f, 0.f, 0.f};
        for (int k4 = 0; k4 < 32; k4++) {
            float pm0 = sPhiPt[(k4*4+0)*16 + m];
            float pm1 = sPhiPt[(k4*4+1)*16 + m];
            float pm2 = sPhiPt[(k4*4+2)*16 + m];
            float pm3 = sPhiPt[(k4*4+3)*16 + m];
            #pragma unroll
            for (int r = 0; r < 4; r++) {
                float4 wv = __ldg(&((const float4*)(W_val + (q*4+r) * 128))[k4]);
                va[r] += pm0*wv.x + pm1*wv.y + pm2*wv.z + pm3*wv.w;
            }
        }
        #pragma unroll
        for (int r = 0; r < 4; r++) sVp[m * 32 + q*4 + r] = va[r];
    }
    __syncthreads();

    if (tid < 32) {
        const int lane = tid;
        const int is64 = detect64(ids);
        const float sizeQ = (float)(load_ll(offs, b + 1, is64) - load_ll(offs, b, is64));
        const float sw0 = size_w[0], sw1 = size_w[1];
        float s[16];
        #pragma unroll
        for (int m = 0; m < 16; m++) {
            float part = 0.f;
            #pragma unroll
            for (int a = lane; a < 128; a += 32) part += sAQ[a] * sBP[m * 128 + a];
            #pragma unroll
            for (int off = 16; off; off >>= 1) part += __shfl_xor_sync(0xffffffffu, part, off);
            double sizeP = g_acc.sizeP[m];
            double sump  = g_acc.sumpS[b * 16 + m];
            double delta = (double)sizeQ + sizeP - 2.0 * sump;
            s[m] = (float)(-0.3 * delta + (double)part
                           + (double)sw0 * (double)sizeQ + (double)sw1 * sizeP);
        }
        float mx = s[0];
        #pragma unroll
        for (int m = 1; m < 16; m++) mx = fmaxf(mx, s[m]);
        float sum = 0.f;
        #pragma unroll
        for (int m = 0; m < 16; m++) { s[m] = expf(s[m] - mx); sum += s[m]; }
        const float inv = 1.f / sum;
        const float bvv = b_val[lane];
        float z = 0.f;
        #pragma unroll
        for (int m = 0; m < 16; m++) z += s[m] * inv * (sVp[m * 32 + lane] + bvv);
        Zs[lane] = z;
    }
    __syncthreads();
    const int j = tid;
    const float4* Wo4 = (const float4*)(W_out + j * 128);
    const float4* Z4  = (const float4*)Zs;
    #pragma unroll
    for (int h = 0; h < 4; h++) {
        float acc = 0.f;
        #pragma unroll
        for (int d = 0; d < 8; d++) {
            float4 wv = __ldg(&Wo4[h * 8 + d]);
            float4 zv = Z4[d];
            acc += zv.x*wv.x + zv.y*wv.y + zv.z*wv.z + zv.w*wv.w;
        }
        g_C[b * 512 + h * 128 + j] = acc;
    }
}

// ---------------- K4: per-token gates + output; 8 tokens per warp ----------------
__global__ __launch_bounds__(256) void k_tokens(const float* __restrict__ ts,
        const float* __restrict__ W_gate, const float* __restrict__ b_gate,
        const float* __restrict__ b_out, float* __restrict__ out) {
    __shared__ float wg[512];
    __shared__ float bo[128];
    __shared__ float bg[4];
    const int tid = threadIdx.x;
    wg[tid] = W_gate[tid];
    wg[tid + 256] = W_gate[tid + 256];
    if (tid < 128) bo[tid] = b_out[tid];
    if (tid < 4)   bg[tid] = b_gate[tid];
    __syncthreads();

    const int w = tid >> 5, lane = tid & 31;
    const int tok0 = (blockIdx.x * 8 + w) * 8;       // 8 consecutive tokens, same b
    const int b = tok0 >> 11;                        // L = 2048, 8 | 2048

    // per-lane invariants held in registers across the 8 tokens
    const float4* wg4 = (const float4*)wg;
    float4 wgr0 = wg4[0 * 32 + lane];
    float4 wgr1 = wg4[1 * 32 + lane];
    float4 wgr2 = wg4[2 * 32 + lane];
    float4 wgr3 = wg4[3 * 32 + lane];
    const float4* C4 = (const float4*)(g_C + b * 512);
    float4 c0 = __ldg(&C4[0 * 32 + lane]);
    float4 c1 = __ldg(&C4[1 * 32 + lane]);
    float4 c2 = __ldg(&C4[2 * 32 + lane]);
    float4 c3 = __ldg(&C4[3 * 32 + lane]);
    const float4 bov = ((const float4*)bo)[lane];
    const float bg0 = bg[0], bg1 = bg[1], bg2 = bg[2], bg3 = bg[3];

    const float4* ts4 = (const float4*)ts;
    float4* out4 = (float4*)out;

    #pragma unroll 2
    for (int t = 0; t < 8; t++) {
        const long long token = tok0 + t;
        const float4 x = __ldg(&ts4[token * 32 + lane]);
        float g0 = x.x*wgr0.x + x.y*wgr0.y + x.z*wgr0.z + x.w*wgr0.w;
        float g1 = x.x*wgr1.x + x.y*wgr1.y + x.z*wgr1.z + x.w*wgr1.w;
        float g2 = x.x*wgr2.x + x.y*wgr2.y + x.z*wgr2.z + x.w*wgr2.w;
        float g3 = x.x*wgr3.x + x.y*wgr3.y + x.z*wgr3.z + x.w*wgr3.w;
        #pragma unroll
        for (int off = 16; off; off >>= 1) {
            g0 += __shfl_xor_sync(0xffffffffu, g0, off);
            g1 += __shfl_xor_sync(0xffffffffu, g1, off);
            g2 += __shfl_xor_sync(0xffffffffu, g2, off);
            g3 += __shfl_xor_sync(0xffffffffu, g3, off);
        }
        g0 += bg0; g1 += bg1; g2 += bg2; g3 += bg3;
        float mx = fmaxf(fmaxf(g0, g1), fmaxf(g2, g3));
        g0 = __expf(g0 - mx); g1 = __expf(g1 - mx);
        g2 = __expf(g2 - mx); g3 = __expf(g3 - mx);
        const float inv = __frcp_rn(g0 + g1 + g2 + g3);
        g0 *= inv; g1 *= inv; g2 *= inv; g3 *= inv;

        float4 o = bov;
        o.x += g0*c0.x + g1*c1.x + g2*c2.x + g3*c3.x;
        o.y += g0*c0.y + g1*c1.y + g2*c2.y + g3*c3.y;
        o.z += g0*c0.z + g1*c1.z + g2*c2.z + g3*c3.z;
        o.w += g0*c0.w + g1*c1.w + g2*c2.w + g3*c3.w;
        out4[token * 32 + lane] = o;
    }
}

// ---------------- launch (serial stream order) ----------------
extern "C" void kernel_launch(void* const* d_in, const int* in_sizes, int n_in,
                              void* d_out, int out_size) {
    const float* ts    = (const float*)d_in[0];
    const void*  ids   = d_in[1];
    const void*  offs  = d_in[2];
    const float* emb   = (const float*)d_in[3];
    const float* phi   = (const float*)d_in[4];
    const float* W_A   = (const float*)d_in[5];
    const float* W_B   = (const float*)d_in[6];
    const float* W_val = (const float*)d_in[7];
    const float* b_val = (const float*)d_in[8];
    const float* W_g   = (const float*)d_in[9];
    const float* b_g   = (const float*)d_in[10];
    const float* W_o   = (const float*)d_in[11];
    const float* b_o   = (const float*)d_in[12];
    const float* szw   = (const float*)d_in[13];

    void* accp = nullptr;
    cudaGetSymbolAddress(&accp, g_acc);
    cudaMemsetAsync(accp, 0, sizeof(Acc), 0);

    k_proto <<<(VV + 255) / 256, 256>>>(phi, emb);
    k_gather<<<BB * 64, 256>>>(ids, offs, emb);
    k_attn  <<<BB, 128>>>(ids, offs, szw, W_A, W_B, W_val, b_val, W_o);
    k_tokens<<<(BB * LL) / 64, 256>>>(ts, W_g, b_g, b_o, (float*)d_out);
}